// round 4
// baseline (speedup 1.0000x reference)
#include <cuda_runtime.h>
#include <math.h>

#define NLAY 4
#define NBAT 16384
#define NR   256

// ---------------- scratch: device globals (no runtime allocation allowed) ----------------
__device__ float g_ugacc[NBAT * 16];                 // [b][l*4+j]  h_stacked @ w_ug part (layer-independent)
__device__ float g_gvals[NBAT * 4];                  // [b][g]      tanh global gates for current layer
__device__ float g_gacc[(size_t)NBAT * NR];          // [b][q]      sum_g g * (h_g @ Wuij^T) (+bias term)
__device__ float g_zr[(size_t)NBAT * 2 * NR];        // [b][0:256]=z pre-act, [256:512]=r pre-act
__device__ float g_cand[(size_t)NBAT * NR];          // [b][q]      x @ w_j1j^T + b

// ---------------- packed fp32x2 (Blackwell FFMA2 — PTX-only instruction) ----------------
__device__ __forceinline__ unsigned long long f2_fma(unsigned long long a, unsigned long long b,
                                                     unsigned long long c) {
    unsigned long long d;
    asm("fma.rn.f32x2 %0, %1, %2, %3;" : "=l"(d) : "l"(a), "l"(b), "l"(c));
    return d;
}
__device__ __forceinline__ unsigned long long f2_dup(float x) {
    unsigned long long d;
    unsigned int u = __float_as_uint(x);
    asm("mov.b64 %0, {%1, %1};" : "=l"(d) : "r"(u));
    return d;
}
__device__ __forceinline__ void f2_unpack(unsigned long long v, float& lo, float& hi) {
    unsigned int l_, h_;
    asm("mov.b64 {%0, %1}, %2;" : "=r"(l_), "=r"(h_) : "l"(v));
    lo = __uint_as_float(l_);
    hi = __uint_as_float(h_);
}

// ---------------- shared 8x(128x128) micro-kernel: acc2[ip][j] packs output rows (2ip, 2ip+1) ----------------
__device__ __forceinline__ void mm_kk8(const float (*As)[128], const float (*Bs)[128],
                                       unsigned long long acc2[4][8], int tm8, int tn8) {
#pragma unroll
    for (int kk = 0; kk < 8; ++kk) {
        ulonglong2 av0 = *(const ulonglong2*)&As[kk][tm8];
        ulonglong2 av1 = *(const ulonglong2*)&As[kk][tm8 + 4];
        unsigned long long a2[4] = {av0.x, av0.y, av1.x, av1.y};
        float4 b0 = *(const float4*)&Bs[kk][tn8];
        float4 b1 = *(const float4*)&Bs[kk][tn8 + 4];
        unsigned long long b2[8] = {f2_dup(b0.x), f2_dup(b0.y), f2_dup(b0.z), f2_dup(b0.w),
                                    f2_dup(b1.x), f2_dup(b1.y), f2_dup(b1.z), f2_dup(b1.w)};
#pragma unroll
        for (int ip = 0; ip < 4; ++ip)
#pragma unroll
            for (int j = 0; j < 8; ++j)
                acc2[ip][j] = f2_fma(a2[ip], b2[j], acc2[ip][j]);
    }
}

// ---------------- generic C[M,N] = A0@W0^T (+ A1@W1^T) + biases  (W: [N,256] row-major) ----------------
__device__ __forceinline__ void sgemm_body(const float* __restrict__ A0, const float* __restrict__ W0,
                                           const float* __restrict__ A1, const float* __restrict__ W1,
                                           const float* __restrict__ b0, const float* __restrict__ b1,
                                           float* __restrict__ C, int N) {
    __shared__ __align__(16) float As[8][128];
    __shared__ __align__(16) float Bs[8][128];
    const int tid = threadIdx.x;
    const int bm = blockIdx.x * 128, bn = blockIdx.y * 128;
    const int tm8 = (tid >> 4) * 8, tn8 = (tid & 15) * 8;
    const int lm = tid >> 1, lk = (tid & 1) * 4;

    unsigned long long acc2[4][8];
#pragma unroll
    for (int i = 0; i < 4; ++i)
#pragma unroll
        for (int j = 0; j < 8; ++j) acc2[i][j] = 0ULL;

    for (int pass = 0; pass < 2; ++pass) {
        const float* A = (pass == 0) ? A0 : A1;
        const float* W = (pass == 0) ? W0 : W1;
        if (A == nullptr) break;
        const float* Ar = A + (size_t)(bm + lm) * 256 + lk;
        const float* Wr = W + (size_t)(bn + lm) * 256 + lk;
#pragma unroll 4
        for (int k0 = 0; k0 < 256; k0 += 8) {
            float4 av = *(const float4*)(Ar + k0);
            float4 wv = *(const float4*)(Wr + k0);
            __syncthreads();
            As[lk + 0][lm] = av.x; As[lk + 1][lm] = av.y;
            As[lk + 2][lm] = av.z; As[lk + 3][lm] = av.w;
            Bs[lk + 0][lm] = wv.x; Bs[lk + 1][lm] = wv.y;
            Bs[lk + 2][lm] = wv.z; Bs[lk + 3][lm] = wv.w;
            __syncthreads();
            mm_kk8(As, Bs, acc2, tm8, tn8);
        }
    }

    float bv[8];
#pragma unroll
    for (int j = 0; j < 8; ++j) {
        int n = bn + tn8 + j;
        float v = b0 ? b0[n] : 0.f;
        if (b1) v += b1[n];
        bv[j] = v;
    }
#pragma unroll
    for (int ip = 0; ip < 4; ++ip) {
        float r0[8], r1[8];
#pragma unroll
        for (int j = 0; j < 8; ++j) {
            f2_unpack(acc2[ip][j], r0[j], r1[j]);
            r0[j] += bv[j];
            r1[j] += bv[j];
        }
        int m0 = bm + tm8 + 2 * ip;
        float4 o;
        o.x = r0[0]; o.y = r0[1]; o.z = r0[2]; o.w = r0[3];
        *(float4*)(C + (size_t)m0 * N + bn + tn8) = o;
        o.x = r0[4]; o.y = r0[5]; o.z = r0[6]; o.w = r0[7];
        *(float4*)(C + (size_t)m0 * N + bn + tn8 + 4) = o;
        o.x = r1[0]; o.y = r1[1]; o.z = r1[2]; o.w = r1[3];
        *(float4*)(C + (size_t)(m0 + 1) * N + bn + tn8) = o;
        o.x = r1[4]; o.y = r1[5]; o.z = r1[6]; o.w = r1[7];
        *(float4*)(C + (size_t)(m0 + 1) * N + bn + tn8 + 4) = o;
    }
}

__global__ void __launch_bounds__(256, 2)
zr_gemm_k(const float* __restrict__ A0, const float* __restrict__ W0,
          const float* __restrict__ A1, const float* __restrict__ W1,
          const float* __restrict__ b0, const float* __restrict__ b1) {
    sgemm_body(A0, W0, A1, W1, b0, b1, g_zr, 512);
}

__global__ void __launch_bounds__(256, 2)
cand_gemm_k(const float* __restrict__ A0, const float* __restrict__ W0, const float* __restrict__ b0) {
    sgemm_body(A0, W0, nullptr, nullptr, b0, nullptr, g_cand, 256);
}

// ---------------- g_acc GEMM: K'=1024 over (g,k); A'[b,g*256+k] = gvals[b,g]*prev[g,b,k] ----------------
__global__ void __launch_bounds__(256, 2)
gacc_gemm_k(const float* __restrict__ prev, const float* __restrict__ wuij,
            const float* __restrict__ buij) {
    __shared__ __align__(16) float As[8][128];
    __shared__ __align__(16) float Bs[8][128];
    const int tid = threadIdx.x;
    const int bm = blockIdx.x * 128, bn = blockIdx.y * 128;
    const int tm8 = (tid >> 4) * 8, tn8 = (tid & 15) * 8;
    const int lm = tid >> 1, lk = (tid & 1) * 4;
    const int arow = bm + lm;

    unsigned long long acc2[4][8];
#pragma unroll
    for (int i = 0; i < 4; ++i)
#pragma unroll
        for (int j = 0; j < 8; ++j) acc2[i][j] = 0ULL;

#pragma unroll 2
    for (int k0 = 0; k0 < 1024; k0 += 8) {
        const int g = k0 >> 8, kl = k0 & 255;
        float sc = g_gvals[arow * 4 + g];
        float4 av = *(const float4*)(prev + ((size_t)g * NBAT + arow) * 256 + kl + lk);
        float4 wv = *(const float4*)(wuij + ((size_t)g * 256 + bn + lm) * 256 + kl + lk);
        av.x *= sc; av.y *= sc; av.z *= sc; av.w *= sc;
        __syncthreads();
        As[lk + 0][lm] = av.x; As[lk + 1][lm] = av.y;
        As[lk + 2][lm] = av.z; As[lk + 3][lm] = av.w;
        Bs[lk + 0][lm] = wv.x; Bs[lk + 1][lm] = wv.y;
        Bs[lk + 2][lm] = wv.z; Bs[lk + 3][lm] = wv.w;
        __syncthreads();
        mm_kk8(As, Bs, acc2, tm8, tn8);
    }

    // epilogue: += sum_g gvals[b,g] * b_uij[l,g,q]
#pragma unroll
    for (int ip = 0; ip < 4; ++ip) {
        float r0[8], r1[8];
#pragma unroll
        for (int j = 0; j < 8; ++j) f2_unpack(acc2[ip][j], r0[j], r1[j]);
        int m0 = bm + tm8 + 2 * ip;
        float ga0 = g_gvals[m0 * 4 + 0], ga1 = g_gvals[m0 * 4 + 1];
        float ga2 = g_gvals[m0 * 4 + 2], ga3 = g_gvals[m0 * 4 + 3];
        float gb0 = g_gvals[(m0 + 1) * 4 + 0], gb1 = g_gvals[(m0 + 1) * 4 + 1];
        float gb2 = g_gvals[(m0 + 1) * 4 + 2], gb3 = g_gvals[(m0 + 1) * 4 + 3];
#pragma unroll
        for (int j = 0; j < 8; ++j) {
            int q = bn + tn8 + j;
            float bq0 = buij[q], bq1 = buij[256 + q], bq2 = buij[512 + q], bq3 = buij[768 + q];
            r0[j] += ga0 * bq0 + ga1 * bq1 + ga2 * bq2 + ga3 * bq3;
            r1[j] += gb0 * bq0 + gb1 * bq1 + gb2 * bq2 + gb3 * bq3;
        }
        float4 o;
        o.x = r0[0]; o.y = r0[1]; o.z = r0[2]; o.w = r0[3];
        *(float4*)(g_gacc + (size_t)m0 * 256 + bn + tn8) = o;
        o.x = r0[4]; o.y = r0[5]; o.z = r0[6]; o.w = r0[7];
        *(float4*)(g_gacc + (size_t)m0 * 256 + bn + tn8 + 4) = o;
        o.x = r1[0]; o.y = r1[1]; o.z = r1[2]; o.w = r1[3];
        *(float4*)(g_gacc + (size_t)(m0 + 1) * 256 + bn + tn8) = o;
        o.x = r1[4]; o.y = r1[5]; o.z = r1[6]; o.w = r1[7];
        *(float4*)(g_gacc + (size_t)(m0 + 1) * 256 + bn + tn8 + 4) = o;
    }
}

// ---------------- h_stacked @ w_ug[l].T for ALL (l,j) at once (prev_hs-only, hoisted out of layer loop) ----------------
// grid (NBAT/8, 2): blockIdx.y selects 8 of the 16 (l,j) pairs; one warp per batch row.
__global__ void ug_precompute_k(const float* __restrict__ prev, const float* __restrict__ wug) {
    __shared__ float ws[8 * 1024];  // 32 KB
    const int ljbase = blockIdx.y * 8;
    {
        const float4* src = (const float4*)(wug + (size_t)ljbase * 1024);
        float4* dst = (float4*)ws;
#pragma unroll
        for (int i = 0; i < 8; ++i) dst[threadIdx.x + i * 256] = src[threadIdx.x + i * 256];
    }
    __syncthreads();
    const int warp = threadIdx.x >> 5, lane = threadIdx.x & 31;
    const int b = blockIdx.x * 8 + warp;
    float acc[8];
#pragma unroll
    for (int t = 0; t < 8; ++t) acc[t] = 0.f;
#pragma unroll
    for (int g = 0; g < 4; ++g) {
        const float* hrow = prev + ((size_t)g * NBAT + b) * 256;
#pragma unroll
        for (int rr = 0; rr < 8; ++rr) {
            int r = rr * 32 + lane;
            float h = hrow[r];
#pragma unroll
            for (int t = 0; t < 8; ++t) acc[t] += h * ws[t * 1024 + g * 256 + r];
        }
    }
#pragma unroll
    for (int t = 0; t < 8; ++t) {
        float v = acc[t];
#pragma unroll
        for (int o = 16; o > 0; o >>= 1) v += __shfl_xor_sync(0xffffffffu, v, o);
        if (lane == 0) g_ugacc[(size_t)b * 16 + ljbase + t] = v;
    }
}

// ---------------- per-layer global gates: g[b,j] = tanh(x_l . w_g[l,j] + ugacc + biases) ----------------
__global__ void xg_k(const float* __restrict__ xl, const float* __restrict__ wg,
                     const float* __restrict__ bg, const float* __restrict__ bug, int l) {
    __shared__ float ws[1024];
#pragma unroll
    for (int i = 0; i < 4; ++i) ws[threadIdx.x + i * 256] = wg[threadIdx.x + i * 256];
    __syncthreads();
    const int warp = threadIdx.x >> 5, lane = threadIdx.x & 31;
    const int b = blockIdx.x * 8 + warp;
    const float* xrow = xl + (size_t)b * 256;
    float acc[4] = {0.f, 0.f, 0.f, 0.f};
#pragma unroll
    for (int rr = 0; rr < 8; ++rr) {
        int r = rr * 32 + lane;
        float xv = xrow[r];
#pragma unroll
        for (int j = 0; j < 4; ++j) acc[j] += xv * ws[j * 256 + r];
    }
#pragma unroll
    for (int j = 0; j < 4; ++j) {
        float v = acc[j];
#pragma unroll
        for (int o = 16; o > 0; o >>= 1) v += __shfl_xor_sync(0xffffffffu, v, o);
        if (lane == 0)
            g_gvals[b * 4 + j] = tanhf(v + g_ugacc[(size_t)b * 16 + l * 4 + j] + bg[j] + bug[j]);
    }
}

// ---------------- final GRU pointwise ----------------
__global__ void pointwise_k(const float* __restrict__ hprev, float* __restrict__ out) {
    size_t idx = (size_t)blockIdx.x * 256 + threadIdx.x;
    int b = (int)(idx >> 8);
    int r = (int)(idx & 255);
    float zpre = g_zr[(size_t)b * 512 + r];
    float rpre = g_zr[(size_t)b * 512 + 256 + r];
    float z = 1.f / (1.f + expf(-zpre));
    float rt = 1.f / (1.f + expf(-rpre));
    float hc = tanhf(g_cand[idx] + rt * g_gacc[idx]);
    float hp = hprev[idx];
    out[idx] = (1.f - z) * hp + z * hc;
}

// ---------------- launch ----------------
extern "C" void kernel_launch(void* const* d_in, const int* in_sizes, int n_in,
                              void* d_out, int out_size) {
    (void)in_sizes; (void)n_in; (void)out_size;
    const float* x     = (const float*)d_in[0];
    const float* prev  = (const float*)d_in[1];
    const float* w_i2h = (const float*)d_in[2];
    const float* b_i2h = (const float*)d_in[3];
    const float* w_h2h = (const float*)d_in[4];
    const float* b_h2h = (const float*)d_in[5];
    const float* w_j1j = (const float*)d_in[6];
    const float* b_j1j = (const float*)d_in[7];
    const float* w_g   = (const float*)d_in[8];
    const float* b_g   = (const float*)d_in[9];
    const float* w_ug  = (const float*)d_in[10];
    const float* b_ug  = (const float*)d_in[11];
    const float* w_uij = (const float*)d_in[12];
    const float* b_uij = (const float*)d_in[13];
    float* out = (float*)d_out;

    // layer-independent: h_stacked @ w_ug[l].T for all (l, j)
    ug_precompute_k<<<dim3(NBAT / 8, 2), 256>>>(prev, w_ug);

    for (int l = 0; l < NLAY; ++l) {
        const float* xl = (l == 0) ? x : out + (size_t)(l - 1) * NBAT * NR;

        // global gates for this layer (needs x_l)
        xg_k<<<NBAT / 8, 256>>>(xl, w_g + (size_t)l * 4 * 256, b_g + l * 4, b_ug + l * 4, l);

        // g_acc = sum_g g[b,g] * (h_g @ Wuij[l,g]^T + b_uij[l,g])   [fused, no uij materialization]
        gacc_gemm_k<<<dim3(NBAT / 128, 2), 256>>>(prev, w_uij + (size_t)l * 4 * 256 * 256,
                                                  b_uij + (size_t)l * 4 * 256);

        // z/r pre-activations: x@w_i2h^T + h_l@w_h2h^T + biases   [B,512]
        zr_gemm_k<<<dim3(NBAT / 128, 4), 256>>>(xl, w_i2h + (size_t)l * 512 * 256,
                                                prev + (size_t)l * NBAT * 256,
                                                w_h2h + (size_t)l * 512 * 256,
                                                b_i2h + (size_t)l * 512, b_h2h + (size_t)l * 512);

        // candidate linear part: x@w_j1j^T + b   [B,256]
        cand_gemm_k<<<dim3(NBAT / 128, 2), 256>>>(xl, w_j1j + (size_t)l * 256 * 256,
                                                  b_j1j + (size_t)l * 256);

        // ht = (1-z)*h_prev + z*tanh(cand + r*g_acc)
        pointwise_k<<<(NBAT * NR) / 256, 256>>>(prev + (size_t)l * NBAT * 256,
                                                out + (size_t)l * NBAT * 256);
    }
}